// round 16
// baseline (speedup 1.0000x reference)
#include <cuda_runtime.h>
#include <cuda_fp16.h>
#include <cstdint>

#define DEVINL static __device__ __forceinline__

// ===================== compile-time int-list machinery =====================
template<int... Is> struct IL { static constexpr int size = sizeof...(Is); };

template<int H, typename L> struct Prepend;
template<int H, int... Is> struct Prepend<H, IL<Is...>> { using type = IL<H, Is...>; };

template<typename A, typename B> struct Concat;
template<int... As, int... Bs> struct Concat<IL<As...>, IL<Bs...>> { using type = IL<As..., Bs...>; };

template<int I, typename L> struct Get;
template<int H, int... T> struct Get<0, IL<H, T...>> { static constexpr int value = H; };
template<int I, int H, int... T> struct Get<I, IL<H, T...>> { static constexpr int value = Get<I-1, IL<T...>>::value; };

template<int N, typename L> struct Take;
template<> struct Take<0, IL<>> { using type = IL<>; };
template<int H, int... T> struct Take<0, IL<H, T...>> { using type = IL<>; };
template<int N, int H, int... T> struct Take<N, IL<H, T...>> {
  using type = typename Prepend<H, typename Take<N-1, IL<T...>>::type>::type;
};

template<int N, typename L> struct Drop;
template<> struct Drop<0, IL<>> { using type = IL<>; };
template<int H, int... T> struct Drop<0, IL<H, T...>> { using type = IL<H, T...>; };
template<int N, int H, int... T> struct Drop<N, IL<H, T...>> { using type = typename Drop<N-1, IL<T...>>::type; };

template<typename L> struct EvenOdd;
template<> struct EvenOdd<IL<>> { using even = IL<>; using odd = IL<>; };
template<int A> struct EvenOdd<IL<A>> { using even = IL<A>; using odd = IL<>; };
template<int A, int Bv, int... R> struct EvenOdd<IL<A, Bv, R...>> {
  using even = typename Prepend<A,  typename EvenOdd<IL<R...>>::even>::type;
  using odd  = typename Prepend<Bv, typename EvenOdd<IL<R...>>::odd >::type;
};

template<typename E, typename O> struct Interleave;
template<typename E> struct Interleave<E, IL<>> { using type = E; };
template<int E0, int... Es, int O0, int... Os>
struct Interleave<IL<E0, Es...>, IL<O0, Os...>> {
  using type = typename Concat<IL<E0, O0>, typename Interleave<IL<Es...>, IL<Os...>>::type>::type;
};

// ===================== packed f16x2 compare-exchange =====================
DEVINL void cas_(__half2& x, __half2& y) {
  __half2 lo = __hmin2(x, y);
  __half2 hi = __hmax2(x, y);
  x = lo; y = hi;
}

// cleanup step of odd-even merge: cas(O[i], E[i+1])
template<typename E, typename O> struct Cleanup {
  DEVINL void run(__half2*) {}
};
template<int E0, int E1, int... Es, int O0, int... Os>
struct Cleanup<IL<E0, E1, Es...>, IL<O0, Os...>> {
  DEVINL void run(__half2* v) {
    cas_(v[O0], v[E1]);
    Cleanup<IL<E1, Es...>, IL<Os...>>::run(v);
  }
};

// ===================== generalized Batcher odd-even merge =====================
template<typename A, typename B, int M = A::size, int N = B::size>
struct Merge {
  using ME = Merge<typename EvenOdd<A>::even, typename EvenOdd<B>::even>;
  using MO = Merge<typename EvenOdd<A>::odd,  typename EvenOdd<B>::odd >;
  using E = typename ME::type;
  using O = typename MO::type;
  using type = typename Interleave<E, O>::type;
  DEVINL void run(__half2* v) { ME::run(v); MO::run(v); Cleanup<E, O>::run(v); }
};
template<typename A, typename B, int N> struct Merge<A, B, 0, N> { using type = B; DEVINL void run(__half2*) {} };
template<typename A, typename B, int M> struct Merge<A, B, M, 0> { using type = A; DEVINL void run(__half2*) {} };
template<typename A, typename B>        struct Merge<A, B, 0, 0> { using type = IL<>; DEVINL void run(__half2*) {} };
template<typename A, typename B> struct Merge<A, B, 1, 1> {
  static constexpr int a0 = Get<0, A>::value;
  static constexpr int b0 = Get<0, B>::value;
  using type = IL<a0, b0>;
  DEVINL void run(__half2* v) { cas_(v[a0], v[b0]); }
};

// odd-even merge sort
template<typename L, int N = L::size>
struct Sort {
  static constexpr int Half = N / 2;
  using SA = Sort<typename Take<Half, L>::type>;
  using SB = Sort<typename Drop<Half, L>::type>;
  using MG = Merge<typename SA::type, typename SB::type>;
  using type = typename MG::type;
  DEVINL void run(__half2* v) { SA::run(v); SB::run(v); MG::run(v); }
};
template<typename L> struct Sort<L, 0> { using type = IL<>; DEVINL void run(__half2*) {} };
template<typename L> struct Sort<L, 1> { using type = L;    DEVINL void run(__half2*) {} };

template<int S, int N> struct Range {
  using type = typename Prepend<S, typename Range<S+1, N-1>::type>::type;
};
template<int S> struct Range<S, 0> { using type = IL<>; };

// ===================== opaque smem ld/st + bit casts =====================
DEVINL uint32_t s2u(const void* p) { return (uint32_t)__cvta_generic_to_shared(p); }
DEVINL void sts_u64(uint32_t a, uint32_t x, uint32_t y) {
  asm volatile("st.shared.v2.u32 [%0], {%1, %2};" :: "r"(a), "r"(x), "r"(y) : "memory");
}
DEVINL void lds_u64(uint32_t a, uint32_t& x, uint32_t& y) {
  asm volatile("ld.shared.v2.u32 {%0, %1}, [%2];" : "=r"(x), "=r"(y) : "r"(a) : "memory");
}
DEVINL uint32_t lds_u(uint32_t a) {
  uint32_t v;
  asm volatile("ld.shared.b32 %0, [%1];" : "=r"(v) : "r"(a) : "memory");
  return v;
}
DEVINL uint32_t h2u(__half2 h) { return *reinterpret_cast<uint32_t*>(&h); }
DEVINL __half2 u2h(uint32_t u) { return *reinterpret_cast<__half2*>(&u); }

// ===================== problem constants =====================
constexpr int Bn = 4, Hn = 256, Wn = 256, Cn = 16;
constexpr int TX = 8, TY = 4;               // 32 output pixels per block
constexpr int TW = TX + 6, TH = TY + 6;     // 14 x 10 haloed tile
constexpr int NPIX = TX * TY;               // 32
constexpr int NTHREADS = NPIX * 4;          // 128: thread = (pixel, channel-quad)
constexpr int NSLOT = 23;                   // staging slots/thread (A[2..24]), 8B each
constexpr int FS = 52;                      // feat / wsmT row stride (16B-aligned)

// single smem pool, two phases:
//   phase 1: tile [0, 4480) + Ast [4480, 28032)
//   phase 2: feat [0, 6656) + wsmT [6656, 9984)
constexpr int SM_TILE = 0;
constexpr int SM_AST  = TH * TW * 8 * 4;                // 4480
constexpr int SM_WT   = NPIX * FS * 4;                  // 6656
constexpr int SM_TOTAL = SM_AST + NTHREADS * NSLOT * 8; // 28032

// Slot layout of V: 0..8 inner 3x3, 9..24 ring of 5x5, 25..48 ring of 7x7
using L9  = Range<0, 9>::type;
using L16 = Range<9, 16>::type;
using L24 = Range<25, 24>::type;
using S9  = Sort<L9>;
using S16 = Sort<L16>;
using S24 = Sort<L24>;
using M25 = Merge<typename S9::type, typename S16::type>;
using A25 = typename M25::type;
using B24 = typename S24::type;

// Stage sorted25 ranks R..24 for BOTH networks (one STS.64 per rank; slot r-2)
template<int R> struct Stage2 {
  DEVINL void run(const __half2* v0, const __half2* v1, uint32_t ab) {
    sts_u64(ab + (R - 2) * 8, h2u(v0[Get<R, A25>::value]), h2u(v1[Get<R, A25>::value]));
    Stage2<R + 1>::run(v0, v1, ab);
  }
};
template<> struct Stage2<25> { DEVINL void run(const __half2*, const __half2*, uint32_t) {} };

// Selection fold: terms t_i = min(a[i-OFS], B24[26-i]) for i = I, I+2, ..., IEnd
template<int I, int IEnd, int OFS> struct SelA {
  DEVINL __half2 run(const __half2* v, const __half2* a) {
    __half2 t = __hmin2(a[I - OFS], v[Get<26 - I, B24>::value]);
    return __hmax2(t, SelA<I + 2, IEnd, OFS>::run(v, a));
  }
};
template<int IEnd, int OFS> struct SelA<IEnd, IEnd, OFS> {
  DEVINL __half2 run(const __half2* v, const __half2* a) {
    return __hmin2(a[IEnd - OFS], v[Get<26 - IEnd, B24>::value]);
  }
};

// rank-26 of union(sorted25 staged at abn, sorted24 in v) for ONE network.
// abn = staging base + net*4; slot r-2 holds rank r (this net's word).
DEVINL __half2 rank26(const __half2* v, uint32_t abn) {
  __half2 a[4];
#pragma unroll
  for (int r = 0; r < 4; r++) a[r] = u2h(lds_u(abn + r * 8));        // ranks 2..5
  __half2 accE = __hmax2(a[0], v[Get<1, B24>::value]);               // A[2], B[1]
  __half2 accO = __hmin2(a[1], v[Get<23, B24>::value]);              // i=3
  accE = __hmax2(accE, __hmin2(a[2], v[Get<22, B24>::value]));       // i=4
  accO = __hmax2(accO, __hmin2(a[3], v[Get<21, B24>::value]));       // i=5
#pragma unroll
  for (int r = 0; r < 4; r++) a[r] = u2h(lds_u(abn + (4 + r) * 8));  // ranks 6..9
  accO = __hmax2(accO, SelA<7, 9, 6>::run(v, a));
  accE = __hmax2(accE, SelA<6, 8, 6>::run(v, a));
#pragma unroll
  for (int r = 0; r < 4; r++) a[r] = u2h(lds_u(abn + (8 + r) * 8));  // ranks 10..13
  accO = __hmax2(accO, SelA<11, 13, 10>::run(v, a));
  accE = __hmax2(accE, SelA<10, 12, 10>::run(v, a));
#pragma unroll
  for (int r = 0; r < 4; r++) a[r] = u2h(lds_u(abn + (12 + r) * 8)); // ranks 14..17
  accO = __hmax2(accO, SelA<15, 17, 14>::run(v, a));
  accE = __hmax2(accE, SelA<14, 16, 14>::run(v, a));
#pragma unroll
  for (int r = 0; r < 4; r++) a[r] = u2h(lds_u(abn + (16 + r) * 8)); // ranks 18..21
  accO = __hmax2(accO, SelA<19, 21, 18>::run(v, a));
  accE = __hmax2(accE, SelA<18, 20, 18>::run(v, a));
#pragma unroll
  for (int r = 0; r < 3; r++) a[r] = u2h(lds_u(abn + (20 + r) * 8)); // ranks 22..24
  accE = __hmax2(accE, SelA<22, 24, 22>::run(v, a));
  accO = __hmax2(accO, SelA<23, 23, 22>::run(v, a));
  return __hmax2(accE, accO);
}

__global__ void __launch_bounds__(NTHREADS, 8)
amblock_kernel(const float* __restrict__ x, const float* __restrict__ w,
               float* __restrict__ out) {
  __shared__ __align__(16) char pool[SM_TOTAL];

  uint32_t* tile = reinterpret_cast<uint32_t*>(pool + SM_TILE); // [TH*TW][8]
  float*    feat = reinterpret_cast<float*>(pool);              // [NPIX][FS] (phase 2)
  float*    wsmT = reinterpret_cast<float*>(pool + SM_WT);      // [16][FS]   (phase 2)

  const int tid = threadIdx.x;
  const int bx = blockIdx.x, by = blockIdx.y, bz = blockIdx.z;

  // haloed tile -> smem as half2; float4 global loads (4 channels/op)
  const int y0 = by * TY - 3, x0 = bx * TX - 3;
  for (int i = tid; i < TH * TW * 4; i += NTHREADS) {
    int q   = i & 3;
    int pos = i >> 2;
    int py = pos / TW, px = pos - py * TW;
    int gy = y0 + py, gx = x0 + px;
    uint2 vv; vv.x = 0u; vv.y = 0u;
    if ((unsigned)gy < (unsigned)Hn && (unsigned)gx < (unsigned)Wn) {
      const float4 f = *reinterpret_cast<const float4*>(
          &x[(((bz * Hn + gy) * Wn) + gx) * Cn + q * 4]);
      vv.x = h2u(__floats2half2_rn(f.x, f.y));
      vv.y = h2u(__floats2half2_rn(f.z, f.w));
    }
    *reinterpret_cast<uint2*>(&tile[pos * 8 + q * 2]) = vv;
  }
  __syncthreads();

  const int q   = tid & 3;           // channel quad: nets cover pairs 2q, 2q+1
  const int pix = tid >> 2;          // 0..31
  __half2 m7_0, m7_1, m3_0, m3_1, m5_0, m5_1;
  {
    const int pxx = pix & (TX - 1);
    const int pyy = pix >> 3;
    const uint32_t tb = s2u(&tile[(((pyy + 3) * TW) + (pxx + 3)) * 8 + q * 2]);
    const uint32_t ab = s2u(pool + SM_AST) + tid * (NSLOT * 8);

    __half2 V0[49], V1[49];
    // inner 3x3 + 5x5 ring, both nets via one LDS.64 per position
    {
      uint32_t vx, vy;
#pragma unroll
      for (int dy = -1; dy <= 1; dy++)
#pragma unroll
        for (int dx = -1; dx <= 1; dx++) {
          lds_u64(tb + (dy * TW + dx) * 32, vx, vy);
          int k = (dy + 1) * 3 + (dx + 1);
          V0[k] = u2h(vx); V1[k] = u2h(vy);
        }
      int k = 9;
#pragma unroll
      for (int dy = -2; dy <= 2; dy++)
#pragma unroll
        for (int dx = -2; dx <= 2; dx++)
          if (dy < -1 || dy > 1 || dx < -1 || dx > 1) {
            lds_u64(tb + (dy * TW + dx) * 32, vx, vy);
            V0[k] = u2h(vx); V1[k] = u2h(vy); k++;
          }
    }

    // k=3 / k=5 for both nets (kept in registers through phase 2)
    S9::run(V0);  S9::run(V1);
    m3_0 = V0[Get<6, typename S9::type>::value];
    m3_1 = V1[Get<6, typename S9::type>::value];
    S16::run(V0); S16::run(V1);
    M25::run(V0); M25::run(V1);
    m5_0 = V0[Get<14, A25>::value];
    m5_1 = V1[Get<14, A25>::value];

    // stage A[2..24] (both nets, uint2 per rank)
    Stage2<2>::run(V0, V1, ab);

    // 7x7 ring -> slots 25..48, both nets (opaque -> cannot hoist above staging)
    {
      uint32_t vx, vy;
      int k = 25;
#pragma unroll
      for (int dy = -3; dy <= 3; dy++)
#pragma unroll
        for (int dx = -3; dx <= 3; dx++)
          if (dy < -2 || dy > 2 || dx < -2 || dx > 2) {
            lds_u64(tb + (dy * TW + dx) * 32, vx, vy);
            V0[k] = u2h(vx); V1[k] = u2h(vy); k++;
          }
    }

    S24::run(V0); S24::run(V1);

    // serialized selections (bounded liveness: V1's B24 held while V0 shrinks)
    m7_0 = rank26(V0, ab);
    m7_1 = rank26(V1, ab + 4);
  }

  // phase 1 data dead; phase 2 overlays it
  __syncthreads();
  {
    float* fp = &feat[pix * FS];
    const float2 a7 = __half22float2(m7_0), b7 = __half22float2(m7_1);
    const float2 a3 = __half22float2(m3_0), b3 = __half22float2(m3_1);
    const float2 a5 = __half22float2(m5_0), b5 = __half22float2(m5_1);
    *reinterpret_cast<float4*>(&fp[     4 * q]) = make_float4(a7.x, a7.y, b7.x, b7.y);
    *reinterpret_cast<float4*>(&fp[16 + 4 * q]) = make_float4(a3.x, a3.y, b3.x, b3.y);
    *reinterpret_cast<float4*>(&fp[32 + 4 * q]) = make_float4(a5.x, a5.y, b5.x, b5.y);
  }
  // transposed weights: wsmT[o*FS+cc] = w[cc*16+o]
  for (int i = tid; i < 16 * 48; i += NTHREADS) {
    int o = i & 15, cc = i >> 4;
    wsmT[o * FS + cc] = w[cc * 16 + o];
  }
  __syncthreads();

  // fused 1x1 conv (fp32): thread computes output channel o for 4 pixels
  {
    const int o = tid & 15;
    const int p = tid >> 4;                  // pixels p, p+8, p+16, p+24
    const float4* wrow = reinterpret_cast<const float4*>(&wsmT[o * FS]);
    const float4* f0 = reinterpret_cast<const float4*>(&feat[p * FS]);
    const float4* f1 = reinterpret_cast<const float4*>(&feat[(p + 8) * FS]);
    const float4* f2 = reinterpret_cast<const float4*>(&feat[(p + 16) * FS]);
    const float4* f3 = reinterpret_cast<const float4*>(&feat[(p + 24) * FS]);
    float acc0 = 0.f, acc1 = 0.f, acc2 = 0.f, acc3 = 0.f;
#pragma unroll
    for (int qq = 0; qq < 12; qq++) {
      const float4 wv = wrow[qq];
      const float4 av = f0[qq], bv = f1[qq], cv = f2[qq], dv = f3[qq];
      acc0 = fmaf(av.x, wv.x, acc0); acc1 = fmaf(bv.x, wv.x, acc1);
      acc2 = fmaf(cv.x, wv.x, acc2); acc3 = fmaf(dv.x, wv.x, acc3);
      acc0 = fmaf(av.y, wv.y, acc0); acc1 = fmaf(bv.y, wv.y, acc1);
      acc2 = fmaf(cv.y, wv.y, acc2); acc3 = fmaf(dv.y, wv.y, acc3);
      acc0 = fmaf(av.z, wv.z, acc0); acc1 = fmaf(bv.z, wv.z, acc1);
      acc2 = fmaf(cv.z, wv.z, acc2); acc3 = fmaf(dv.z, wv.z, acc3);
      acc0 = fmaf(av.w, wv.w, acc0); acc1 = fmaf(bv.w, wv.w, acc1);
      acc2 = fmaf(cv.w, wv.w, acc2); acc3 = fmaf(dv.w, wv.w, acc3);
    }
    // pixel p+8j has pyy=j, pxx=p
    const int gx = bx * TX + p;
#pragma unroll
    for (int j = 0; j < 4; j++) {
      const float acc = (j == 0) ? acc0 : (j == 1) ? acc1 : (j == 2) ? acc2 : acc3;
      out[(((bz * Hn + by * TY + j) * Wn) + gx) * Cn + o] = acc;
    }
  }
}

extern "C" void kernel_launch(void* const* d_in, const int* in_sizes, int n_in,
                              void* d_out, int out_size) {
  const float* x = (const float*)d_in[0];
  const float* w = (const float*)d_in[1];
  float* out = (float*)d_out;
  dim3 grid(Wn / TX, Hn / TY, Bn);
  amblock_kernel<<<grid, NTHREADS>>>(x, w, out);
}